// round 1
// baseline (speedup 1.0000x reference)
#include <cuda_runtime.h>
#include <math.h>

#define NN 16384
#define NE 262144
#define NF 128
#define ND 64
#define NC 40
#define RK 16

// ---------------- scratch (device globals; no allocation allowed) ----------
__device__ float g_xl  [NN * ND];
__device__ float g_h1  [NN * ND];
__device__ float g_h1l [NN * ND];
__device__ float g_h2  [NN * ND];
__device__ float g_aggA[NN * ND];
__device__ float g_aggB[NN * ND];
__device__ float g_cnt [NN];
__device__ float g_phi [NN * RK];
__device__ float g_T   [RK * 65];

// c_k = sqrt(2^k / k!)
__constant__ float c_coef[RK] = {
    1.0f,          1.41421356f,  1.41421356f,  1.15470054f,
    0.81649658f,   0.51639778f,  0.29814240f,  0.15936387f,
    0.07968194f,   0.03756241f,  0.01679842f,  0.00716286f,
    0.00292422f,   0.00114698f,  4.33517e-4f,  1.58298e-4f};

// ---------------- zero scratch used by atomics ------------------------------
__global__ void zero_kernel() {
    int idx = blockIdx.x * blockDim.x + threadIdx.x;
    int stride = gridDim.x * blockDim.x;
    for (int i = idx; i < NN * ND; i += stride) { g_aggA[i] = 0.f; g_aggB[i] = 0.f; }
    for (int i = idx; i < NN; i += stride) g_cnt[i] = 0.f;
    if (idx < RK * 65) g_T[idx] = 0.f;
}

// ---------------- plain GEMM: out[N,64] = A[N,KIN] @ W[KIN,64] -------------
template <int KIN>
__global__ __launch_bounds__(256) void gemm_plain(const float* __restrict__ A,
                                                  const float* __restrict__ W,
                                                  float* __restrict__ out) {
    __shared__ __align__(16) float Ws[KIN * ND];
    for (int i = threadIdx.x; i < KIN * ND; i += 256) Ws[i] = W[i];
    __syncthreads();
    int row = blockIdx.x * 256 + threadIdx.x;
    float acc[ND];
#pragma unroll
    for (int d = 0; d < ND; d++) acc[d] = 0.f;
    const float* a = A + (long)row * KIN;
#pragma unroll 4
    for (int k = 0; k < KIN; k++) {
        float av = __ldg(a + k);
        const float4* w4 = reinterpret_cast<const float4*>(Ws + k * ND);
#pragma unroll
        for (int d4 = 0; d4 < ND / 4; d4++) {
            float4 w = w4[d4];
            acc[4 * d4 + 0] += av * w.x;
            acc[4 * d4 + 1] += av * w.y;
            acc[4 * d4 + 2] += av * w.z;
            acc[4 * d4 + 3] += av * w.w;
        }
    }
    float4* o4 = reinterpret_cast<float4*>(out + (long)row * ND);
#pragma unroll
    for (int d4 = 0; d4 < ND / 4; d4++)
        o4[d4] = make_float4(acc[4 * d4], acc[4 * d4 + 1], acc[4 * d4 + 2], acc[4 * d4 + 3]);
}

// ------ SAGE epilogue GEMM: out = [relu](agg/max(cnt,1) + b + A@W) ----------
template <int KIN, bool RELU>
__global__ __launch_bounds__(256) void sage_gemm(const float* __restrict__ A,
                                                 const float* __restrict__ W,
                                                 const float* __restrict__ bias,
                                                 const float* __restrict__ agg,
                                                 float* __restrict__ out) {
    __shared__ __align__(16) float Ws[KIN * ND];
    __shared__ float bs[ND];
    for (int i = threadIdx.x; i < KIN * ND; i += 256) Ws[i] = W[i];
    if (threadIdx.x < ND) bs[threadIdx.x] = bias[threadIdx.x];
    __syncthreads();
    int row = blockIdx.x * 256 + threadIdx.x;
    float acc[ND];
#pragma unroll
    for (int d = 0; d < ND; d++) acc[d] = 0.f;
    const float* a = A + (long)row * KIN;
#pragma unroll 4
    for (int k = 0; k < KIN; k++) {
        float av = __ldg(a + k);
        const float4* w4 = reinterpret_cast<const float4*>(Ws + k * ND);
#pragma unroll
        for (int d4 = 0; d4 < ND / 4; d4++) {
            float4 w = w4[d4];
            acc[4 * d4 + 0] += av * w.x;
            acc[4 * d4 + 1] += av * w.y;
            acc[4 * d4 + 2] += av * w.z;
            acc[4 * d4 + 3] += av * w.w;
        }
    }
    float inv = 1.f / fmaxf(g_cnt[row], 1.f);
    const float* ag = agg + (long)row * ND;
#pragma unroll
    for (int d = 0; d < ND; d++) {
        float v = __ldg(ag + d) * inv + bs[d] + acc[d];
        if (RELU) v = fmaxf(v, 0.f);
        acc[d] = v;
    }
    float4* o4 = reinterpret_cast<float4*>(out + (long)row * ND);
#pragma unroll
    for (int d4 = 0; d4 < ND / 4; d4++)
        o4[d4] = make_float4(acc[4 * d4], acc[4 * d4 + 1], acc[4 * d4 + 2], acc[4 * d4 + 3]);
}

// ---------------- edge scatter: agg[dst] += val[src]; (cnt on first) -------
template <bool FIRST>
__global__ __launch_bounds__(256) void scatter_kernel(const int* __restrict__ ei,
                                                      const float* __restrict__ val,
                                                      float* __restrict__ agg) {
    int warp = (blockIdx.x * 256 + threadIdx.x) >> 5;
    int lane = threadIdx.x & 31;
    if (warp >= NE) return;
    int src = __ldg(ei + warp);
    int dst = __ldg(ei + NE + warp);
    float v0 = __ldg(val + (long)src * ND + lane);
    float v1 = __ldg(val + (long)src * ND + 32 + lane);
    atomicAdd(agg + (long)dst * ND + lane, v0);
    atomicAdd(agg + (long)dst * ND + 32 + lane, v1);
    if (FIRST && lane == 0) atomicAdd(g_cnt + dst, 1.f);
}

// ---------------- cosine score + rank-16 feature map ------------------------
__global__ __launch_bounds__(256) void score_phi_kernel(const float* __restrict__ aux) {
    __shared__ float s_aux[ND];
    __shared__ float s_inv;
    if (threadIdx.x < ND) s_aux[threadIdx.x] = aux[threadIdx.x];
    __syncthreads();
    if (threadIdx.x == 0) {
        float ss = 0.f;
        for (int d = 0; d < ND; d++) ss += s_aux[d] * s_aux[d];
        s_inv = 1.f / fmaxf(sqrtf(ss), 1e-8f);
    }
    __syncthreads();
    int row = blockIdx.x * 256 + threadIdx.x;
    const float* h = g_h2 + (long)row * ND;
    float dot = 0.f, nn = 0.f;
#pragma unroll
    for (int d = 0; d < ND; d++) {
        float hv = __ldg(h + d);
        dot += hv * s_aux[d];
        nn += hv * hv;
    }
    float s = dot * s_inv / fmaxf(sqrtf(nn), 1e-8f);
    float e = expf(-s * s);
    float p = 1.f;
#pragma unroll
    for (int k = 0; k < RK; k++) {
        g_phi[(long)row * RK + k] = e * c_coef[k] * p;
        p *= s;
    }
}

// ---------------- T = Phi^T [h2 | 1]  (16 x 65) -----------------------------
__global__ __launch_bounds__(256) void phiT_kernel() {
    int gw = (blockIdx.x * 256 + threadIdx.x) >> 5;  // 512 warps total
    int lane = threadIdx.x & 31;
    float accA[RK], accB[RK];
#pragma unroll
    for (int k = 0; k < RK; k++) { accA[k] = 0.f; accB[k] = 0.f; }
    float accD = 0.f;
    const int rows_per_warp = NN / 512;  // 32
    int r0 = gw * rows_per_warp;
    for (int r = r0; r < r0 + rows_per_warp; r++) {
        float pv = (lane < RK) ? g_phi[(long)r * RK + lane] : 0.f;
        float v0 = g_h2[(long)r * ND + lane];
        float v1 = g_h2[(long)r * ND + 32 + lane];
        accD += pv;
#pragma unroll
        for (int k = 0; k < RK; k++) {
            float pk = __shfl_sync(0xffffffffu, pv, k);
            accA[k] += pk * v0;
            accB[k] += pk * v1;
        }
    }
#pragma unroll
    for (int k = 0; k < RK; k++) {
        atomicAdd(&g_T[k * 65 + lane], accA[k]);
        atomicAdd(&g_T[k * 65 + 32 + lane], accB[k]);
    }
    if (lane < RK) atomicAdd(&g_T[lane * 65 + 64], accD);
}

// ---------------- z = Phi T / den;  out = [h2|z] @ Wc + bc ------------------
__global__ __launch_bounds__(128) void final_kernel(const float* __restrict__ Wc,
                                                    const float* __restrict__ bc,
                                                    float* __restrict__ out) {
    __shared__ float Ts[RK * 65];
    __shared__ float Wcs[2 * ND * NC];
    __shared__ float bcs[NC];
    for (int i = threadIdx.x; i < RK * 65; i += 128) Ts[i] = g_T[i];
    for (int i = threadIdx.x; i < 2 * ND * NC; i += 128) Wcs[i] = Wc[i];
    if (threadIdx.x < NC) bcs[threadIdx.x] = bc[threadIdx.x];
    __syncthreads();
    int row = blockIdx.x * 128 + threadIdx.x;
    float phi[RK];
#pragma unroll
    for (int k = 0; k < RK; k++) phi[k] = g_phi[(long)row * RK + k];
    float den = 0.f;
#pragma unroll
    for (int k = 0; k < RK; k++) den += phi[k] * Ts[k * 65 + 64];
    float dinv = 1.f / den;
#pragma unroll
    for (int k = 0; k < RK; k++) phi[k] *= dinv;
    float o[NC];
#pragma unroll
    for (int c = 0; c < NC; c++) o[c] = bcs[c];
    const float* h = g_h2 + (long)row * ND;
#pragma unroll 2
    for (int d = 0; d < ND; d++) {
        float hv = __ldg(h + d);
        float zd = 0.f;
#pragma unroll
        for (int k = 0; k < RK; k++) zd += phi[k] * Ts[k * 65 + d];
        const float* w1 = Wcs + d * NC;
        const float* w2 = Wcs + (ND + d) * NC;
#pragma unroll
        for (int c = 0; c < NC; c++) o[c] += hv * w1[c] + zd * w2[c];
    }
    float* op = out + (long)row * NC;
#pragma unroll
    for (int c = 0; c < NC; c++) op[c] = o[c];
}

// ---------------------------------------------------------------------------
extern "C" void kernel_launch(void* const* d_in, const int* in_sizes, int n_in,
                              void* d_out, int out_size) {
    const float* x   = (const float*)d_in[0];
    const int*   ei  = (const int*)d_in[1];
    const float* W1l = (const float*)d_in[2];
    const float* b1  = (const float*)d_in[3];
    const float* W1r = (const float*)d_in[4];
    const float* W2l = (const float*)d_in[5];
    const float* b2  = (const float*)d_in[6];
    const float* W2r = (const float*)d_in[7];
    const float* aux = (const float*)d_in[8];
    const float* Wc  = (const float*)d_in[9];
    const float* bc  = (const float*)d_in[10];
    float* out = (float*)d_out;

    float *p_xl, *p_h1, *p_h1l, *p_h2, *p_aggA, *p_aggB;
    cudaGetSymbolAddress((void**)&p_xl,   g_xl);
    cudaGetSymbolAddress((void**)&p_h1,   g_h1);
    cudaGetSymbolAddress((void**)&p_h1l,  g_h1l);
    cudaGetSymbolAddress((void**)&p_h2,   g_h2);
    cudaGetSymbolAddress((void**)&p_aggA, g_aggA);
    cudaGetSymbolAddress((void**)&p_aggB, g_aggB);

    zero_kernel<<<256, 256>>>();

    // ---- layer 1: h1 = relu(mean_agg(x@W1l) + b1 + x@W1r) ----
    gemm_plain<NF><<<NN / 256, 256>>>(x, W1l, p_xl);
    scatter_kernel<true><<<NE / 8, 256>>>(ei, p_xl, p_aggA);
    sage_gemm<NF, true><<<NN / 256, 256>>>(x, W1r, b1, p_aggA, p_h1);

    // ---- layer 2: h2 = mean_agg(h1@W2l) + b2 + h1@W2r ----
    gemm_plain<ND><<<NN / 256, 256>>>(p_h1, W2l, p_h1l);
    scatter_kernel<false><<<NE / 8, 256>>>(ei, p_h1l, p_aggB);
    sage_gemm<ND, false><<<NN / 256, 256>>>(p_h1, W2r, b2, p_aggB, p_h2);

    // ---- rank-16 separable Gaussian kernel aggregation ----
    score_phi_kernel<<<NN / 256, 256>>>(aux);
    phiT_kernel<<<64, 256>>>();

    // ---- z + classifier ----
    final_kernel<<<NN / 128, 128>>>(Wc, bc, out);
}

// round 2
// speedup vs baseline: 1.7764x; 1.7764x over previous
#include <cuda_runtime.h>
#include <math.h>

#define NN 16384
#define NE 262144
#define NF 128
#define ND 64
#define NC 40
#define RK 16

// ---------------- scratch (device globals; no allocation allowed) ----------
__device__ float g_xl  [NN * ND];   // x @ W1l   (scattered in layer 1)
__device__ float g_xr  [NN * ND];   // x @ W1r   (self part layer 1)
__device__ float g_h1  [NN * ND];
__device__ float g_h1l [NN * ND];   // h1 @ W2l  (scattered in layer 2)
__device__ float g_h1r [NN * ND];   // h1 @ W2r  (self part layer 2)
__device__ float g_h2  [NN * ND];
__device__ float g_aggA[NN * ND];
__device__ float g_aggB[NN * ND];
__device__ float g_cnt [NN];
__device__ float g_phi [NN * RK];
__device__ float g_T   [RK * 65];

// c_k = sqrt(2^k / k!)
__constant__ float c_coef[RK] = {
    1.0f,          1.41421356f,  1.41421356f,  1.15470054f,
    0.81649658f,   0.51639778f,  0.29814240f,  0.15936387f,
    0.07968194f,   0.03756241f,  0.01679842f,  0.00716286f,
    0.00292422f,   0.00114698f,  4.33517e-4f,  1.58298e-4f};

// ---------------- zero scratch used by atomics ------------------------------
__global__ void zero_kernel() {
    int idx = blockIdx.x * blockDim.x + threadIdx.x;
    int stride = gridDim.x * blockDim.x;
    float4 z = make_float4(0.f, 0.f, 0.f, 0.f);
    float4* a = reinterpret_cast<float4*>(g_aggA);
    float4* b = reinterpret_cast<float4*>(g_aggB);
    for (int i = idx; i < NN * ND / 4; i += stride) { a[i] = z; b[i] = z; }
    for (int i = idx; i < NN; i += stride) g_cnt[i] = 0.f;
    if (idx < RK * 65) g_T[idx] = 0.f;
}

// ---- fused dual GEMM: outl = A @ Wl, outr = A @ Wr  (A:[NN,K], W:[K,64]) ---
// Block: 256 threads, M-tile = 128 rows, N = 128 (two 64-wide halves).
// Thread tile 8x8. A staged transposed in smem (chunks of 16 k), W chunked.
template <int K>
__global__ __launch_bounds__(256, 2) void gemm_dual(const float* __restrict__ A,
                                                    const float* __restrict__ Wl,
                                                    const float* __restrict__ Wr,
                                                    float* __restrict__ outl,
                                                    float* __restrict__ outr) {
    constexpr int KC = 16;
    __shared__ __align__(16) float sA[KC * 132];   // [k][m], pad 132 for banks/align
    __shared__ __align__(16) float sW[KC * 128];   // [k][n]  n<64: Wl, n>=64: Wr

    const int tid = threadIdx.x;
    const int mg = tid >> 4;          // 0..15 : row group (8 rows)
    const int ng = tid & 15;          // 0..15 : col group (8 cols)
    const int m_base = blockIdx.x * 128;

    float acc[8][8];
#pragma unroll
    for (int i = 0; i < 8; i++)
#pragma unroll
        for (int j = 0; j < 8; j++) acc[i][j] = 0.f;

    for (int kk = 0; kk < K; kk += KC) {
        __syncthreads();
        // load A chunk transposed: 128 rows x 16 k
#pragma unroll
        for (int j = 0; j < 8; j++) {
            int i = tid + 256 * j;          // 0..2047
            int m = i >> 4;                 // 0..127
            int k = i & 15;
            sA[k * 132 + m] = __ldg(A + (long)(m_base + m) * K + kk + k);
        }
        // load W chunk: 16 k x 128 n
#pragma unroll
        for (int j = 0; j < 8; j++) {
            int i = tid + 256 * j;          // 0..2047
            int k = i >> 7;                 // 0..15
            int n = i & 127;
            float w = (n < 64) ? __ldg(Wl + (long)(kk + k) * 64 + n)
                               : __ldg(Wr + (long)(kk + k) * 64 + (n - 64));
            sW[k * 128 + n] = w;
        }
        __syncthreads();

#pragma unroll 4
        for (int k = 0; k < KC; k++) {
            const float4* a4 = reinterpret_cast<const float4*>(sA + k * 132);
            const float4* w4 = reinterpret_cast<const float4*>(sW + k * 128);
            float4 a0 = a4[mg * 2], a1 = a4[mg * 2 + 1];
            float4 w0 = w4[ng * 2], w1 = w4[ng * 2 + 1];
            float av[8] = {a0.x, a0.y, a0.z, a0.w, a1.x, a1.y, a1.z, a1.w};
            float wv[8] = {w0.x, w0.y, w0.z, w0.w, w1.x, w1.y, w1.z, w1.w};
#pragma unroll
            for (int i = 0; i < 8; i++)
#pragma unroll
                for (int j = 0; j < 8; j++) acc[i][j] += av[i] * wv[j];
        }
    }

    float* outp = (ng < 8) ? outl : outr;
    int cb = (ng & 7) * 8;
#pragma unroll
    for (int i = 0; i < 8; i++) {
        long r = m_base + mg * 8 + i;
        float4* o4 = reinterpret_cast<float4*>(outp + r * ND + cb);
        o4[0] = make_float4(acc[i][0], acc[i][1], acc[i][2], acc[i][3]);
        o4[1] = make_float4(acc[i][4], acc[i][5], acc[i][6], acc[i][7]);
    }
}

// ---------------- edge scatter with vec4 reduction atomics ------------------
template <bool FIRST>
__global__ __launch_bounds__(256) void scatter_kernel(const int* __restrict__ ei,
                                                      const float* __restrict__ val,
                                                      float* __restrict__ agg) {
    int t = blockIdx.x * 256 + threadIdx.x;
    int e = t >> 4;            // 16 threads per edge
    int c = t & 15;            // float4 index within 64-dim row
    int src = __ldg(ei + e);
    int dst = __ldg(ei + NE + e);
    float4 v = __ldg(reinterpret_cast<const float4*>(val + (long)src * ND) + c);
    float* p = agg + (long)dst * ND + c * 4;
    asm volatile("red.global.add.v4.f32 [%0], {%1, %2, %3, %4};"
                 :: "l"(p), "f"(v.x), "f"(v.y), "f"(v.z), "f"(v.w)
                 : "memory");
    if (FIRST && c == 0) atomicAdd(g_cnt + dst, 1.f);
}

// -------- SAGE epilogue: out = [relu](agg/max(cnt,1) + b + self) ------------
template <bool RELU>
__global__ __launch_bounds__(256) void epi_kernel(const float* __restrict__ agg,
                                                  const float* __restrict__ selfp,
                                                  const float* __restrict__ bias,
                                                  float* __restrict__ out) {
    __shared__ float4 bs[16];
    if (threadIdx.x < 16) bs[threadIdx.x] = reinterpret_cast<const float4*>(bias)[threadIdx.x];
    __syncthreads();
    int idx = blockIdx.x * 256 + threadIdx.x;   // over NN*16 float4s
    int row = idx >> 4;
    int q = idx & 15;
    float inv = 1.f / fmaxf(g_cnt[row], 1.f);
    float4 a = __ldg(reinterpret_cast<const float4*>(agg) + idx);
    float4 s = __ldg(reinterpret_cast<const float4*>(selfp) + idx);
    float4 b = bs[q];
    float4 v = make_float4(a.x * inv + b.x + s.x, a.y * inv + b.y + s.y,
                           a.z * inv + b.z + s.z, a.w * inv + b.w + s.w);
    if (RELU) {
        v.x = fmaxf(v.x, 0.f); v.y = fmaxf(v.y, 0.f);
        v.z = fmaxf(v.z, 0.f); v.w = fmaxf(v.w, 0.f);
    }
    reinterpret_cast<float4*>(out)[idx] = v;
}

// ---------------- cosine score + rank-16 feature map ------------------------
__global__ __launch_bounds__(256) void score_phi_kernel(const float* __restrict__ aux) {
    __shared__ float s_aux[ND];
    __shared__ float s_inv;
    if (threadIdx.x < ND) s_aux[threadIdx.x] = aux[threadIdx.x];
    __syncthreads();
    if (threadIdx.x == 0) {
        float ss = 0.f;
        for (int d = 0; d < ND; d++) ss += s_aux[d] * s_aux[d];
        s_inv = 1.f / fmaxf(sqrtf(ss), 1e-8f);
    }
    __syncthreads();
    int row = blockIdx.x * 256 + threadIdx.x;
    const float* h = g_h2 + (long)row * ND;
    float dot = 0.f, nn = 0.f;
#pragma unroll
    for (int d = 0; d < ND; d++) {
        float hv = __ldg(h + d);
        dot += hv * s_aux[d];
        nn += hv * hv;
    }
    float s = dot * s_inv / fmaxf(sqrtf(nn), 1e-8f);
    float e = expf(-s * s);
    float p = 1.f;
#pragma unroll
    for (int k = 0; k < RK; k++) {
        g_phi[(long)row * RK + k] = e * c_coef[k] * p;
        p *= s;
    }
}

// ---------------- T = Phi^T [h2 | 1]  (16 x 65) -----------------------------
__global__ __launch_bounds__(256) void phiT_kernel() {
    int gw = (blockIdx.x * 256 + threadIdx.x) >> 5;  // 512 warps total
    int lane = threadIdx.x & 31;
    float accA[RK], accB[RK];
#pragma unroll
    for (int k = 0; k < RK; k++) { accA[k] = 0.f; accB[k] = 0.f; }
    float accD = 0.f;
    const int rows_per_warp = NN / 512;  // 32
    int r0 = gw * rows_per_warp;
    for (int r = r0; r < r0 + rows_per_warp; r++) {
        float pv = (lane < RK) ? g_phi[(long)r * RK + lane] : 0.f;
        float v0 = g_h2[(long)r * ND + lane];
        float v1 = g_h2[(long)r * ND + 32 + lane];
        accD += pv;
#pragma unroll
        for (int k = 0; k < RK; k++) {
            float pk = __shfl_sync(0xffffffffu, pv, k);
            accA[k] += pk * v0;
            accB[k] += pk * v1;
        }
    }
#pragma unroll
    for (int k = 0; k < RK; k++) {
        atomicAdd(&g_T[k * 65 + lane], accA[k]);
        atomicAdd(&g_T[k * 65 + 32 + lane], accB[k]);
    }
    if (lane < RK) atomicAdd(&g_T[lane * 65 + 64], accD);
}

// ---------------- z = Phi T / den;  out = [h2|z] @ Wc + bc ------------------
__global__ __launch_bounds__(128) void final_kernel(const float* __restrict__ Wc,
                                                    const float* __restrict__ bc,
                                                    float* __restrict__ out) {
    __shared__ float Ts[RK * 65];
    __shared__ float Wcs[2 * ND * NC];
    __shared__ float bcs[NC];
    for (int i = threadIdx.x; i < RK * 65; i += 128) Ts[i] = g_T[i];
    for (int i = threadIdx.x; i < 2 * ND * NC; i += 128) Wcs[i] = Wc[i];
    if (threadIdx.x < NC) bcs[threadIdx.x] = bc[threadIdx.x];
    __syncthreads();
    int row = blockIdx.x * 128 + threadIdx.x;
    float phi[RK];
#pragma unroll
    for (int k = 0; k < RK; k++) phi[k] = g_phi[(long)row * RK + k];
    float den = 0.f;
#pragma unroll
    for (int k = 0; k < RK; k++) den += phi[k] * Ts[k * 65 + 64];
    float dinv = 1.f / den;
#pragma unroll
    for (int k = 0; k < RK; k++) phi[k] *= dinv;
    float o[NC];
#pragma unroll
    for (int c = 0; c < NC; c++) o[c] = bcs[c];
    const float* h = g_h2 + (long)row * ND;
#pragma unroll 2
    for (int d = 0; d < ND; d++) {
        float hv = __ldg(h + d);
        float zd = 0.f;
#pragma unroll
        for (int k = 0; k < RK; k++) zd += phi[k] * Ts[k * 65 + d];
        const float* w1 = Wcs + d * NC;
        const float* w2 = Wcs + (ND + d) * NC;
#pragma unroll
        for (int c = 0; c < NC; c++) o[c] += hv * w1[c] + zd * w2[c];
    }
    float* op = out + (long)row * NC;
#pragma unroll
    for (int c = 0; c < NC; c++) op[c] = o[c];
}

// ---------------------------------------------------------------------------
extern "C" void kernel_launch(void* const* d_in, const int* in_sizes, int n_in,
                              void* d_out, int out_size) {
    const float* x   = (const float*)d_in[0];
    const int*   ei  = (const int*)d_in[1];
    const float* W1l = (const float*)d_in[2];
    const float* b1  = (const float*)d_in[3];
    const float* W1r = (const float*)d_in[4];
    const float* W2l = (const float*)d_in[5];
    const float* b2  = (const float*)d_in[6];
    const float* W2r = (const float*)d_in[7];
    const float* aux = (const float*)d_in[8];
    const float* Wc  = (const float*)d_in[9];
    const float* bc  = (const float*)d_in[10];
    float* out = (float*)d_out;

    float *p_xl, *p_xr, *p_h1, *p_h1l, *p_h1r, *p_h2, *p_aggA, *p_aggB;
    cudaGetSymbolAddress((void**)&p_xl,   g_xl);
    cudaGetSymbolAddress((void**)&p_xr,   g_xr);
    cudaGetSymbolAddress((void**)&p_h1,   g_h1);
    cudaGetSymbolAddress((void**)&p_h1l,  g_h1l);
    cudaGetSymbolAddress((void**)&p_h1r,  g_h1r);
    cudaGetSymbolAddress((void**)&p_h2,   g_h2);
    cudaGetSymbolAddress((void**)&p_aggA, g_aggA);
    cudaGetSymbolAddress((void**)&p_aggB, g_aggB);

    zero_kernel<<<512, 256>>>();

    // ---- layer 1: h1 = relu(mean_agg(x@W1l) + b1 + x@W1r) ----
    gemm_dual<NF><<<NN / 128, 256>>>(x, W1l, W1r, p_xl, p_xr);
    scatter_kernel<true><<<NE * 16 / 256, 256>>>(ei, p_xl, p_aggA);
    epi_kernel<true><<<NN * 16 / 256, 256>>>(p_aggA, p_xr, b1, p_h1);

    // ---- layer 2: h2 = mean_agg(h1@W2l) + b2 + h1@W2r ----
    gemm_dual<ND><<<NN / 128, 256>>>(p_h1, W2l, W2r, p_h1l, p_h1r);
    scatter_kernel<false><<<NE * 16 / 256, 256>>>(ei, p_h1l, p_aggB);
    epi_kernel<false><<<NN * 16 / 256, 256>>>(p_aggB, p_h1r, b2, p_h2);

    // ---- rank-16 separable Gaussian kernel aggregation ----
    score_phi_kernel<<<NN / 256, 256>>>(aux);
    phiT_kernel<<<64, 256>>>();

    // ---- z + classifier ----
    final_kernel<<<NN / 128, 128>>>(Wc, bc, out);
}